// round 14
// baseline (speedup 1.0000x reference)
#include <cuda_runtime.h>
#include <cuda_bf16.h>
#include <math.h>

typedef unsigned long long ull;

// ---------------- problem constants ----------------
#define BB 64
#define SS 8
#define TT 8192
#define L1_LEN 8190
#define L2_LEN 8184
#define L3_LEN 8166

// ---------------- packed f32x2 helpers ----------------
__device__ __forceinline__ ull pk2(float lo, float hi) {
    ull r; asm("mov.b64 %0, {%1, %2};" : "=l"(r) : "f"(lo), "f"(hi)); return r;
}
__device__ __forceinline__ void up2(ull v, float& lo, float& hi) {
    asm("mov.b64 {%0, %1}, %2;" : "=f"(lo), "=f"(hi) : "l"(v));
}
__device__ __forceinline__ void fma2(ull& d, ull a, ull b) {
    asm("fma.rn.f32x2 %0, %1, %2, %0;" : "+l"(d) : "l"(a), "l"(b));
}

// ---------------- device scratch ----------------
__device__ float g_x0[(size_t)BB * 8  * TT];   // eeg after 1x1 head
__device__ float g_x3[(size_t)BB * 16 * TT];   // eeg final features
__device__ float g_nx[BB * 16];                // eeg norms
__device__ float g_nst2[BB * SS * 16];         // stim sumsq accumulators
__device__ float g_dot[(size_t)BB * SS * 256]; // dot accumulators

// ---------------- kernel 1: eeg 1x1 head (64 -> 8) ----------------
__global__ void k_head(const float* __restrict__ eeg,
                       const float* __restrict__ w,
                       const float* __restrict__ bias)
{
    __shared__ float sh_w[512];
    __shared__ float sh_b[8];
    int tid = threadIdx.x;
    for (int i = tid; i < 512; i += 256) sh_w[i] = w[i];
    if (tid < 8) sh_b[tid] = bias[tid];
    __syncthreads();

    size_t idx = (size_t)blockIdx.x * 256 + tid;
    int b = (int)(idx >> 13);
    int t = (int)(idx & (TT - 1));

    const float4* ep = (const float4*)(eeg + idx * 64);
    float acc[8];
#pragma unroll
    for (int c = 0; c < 8; c++) acc[c] = sh_b[c];
#pragma unroll
    for (int q = 0; q < 16; q++) {
        float4 v = ep[q];
#pragma unroll
        for (int c = 0; c < 8; c++) {
            acc[c] += v.x * sh_w[c * 64 + q * 4 + 0]
                    + v.y * sh_w[c * 64 + q * 4 + 1]
                    + v.z * sh_w[c * 64 + q * 4 + 2]
                    + v.w * sh_w[c * 64 + q * 4 + 3];
        }
    }
    float* ob = g_x0 + ((size_t)b * 8) * TT + t;
#pragma unroll
    for (int c = 0; c < 8; c++) ob[(size_t)c * TT] = acc[c];
}

// ---------------- R13 conv body (float shared, used by eeg stack) ----------------
template <int CIN, int DIL, int NT>
__device__ __forceinline__ void conv_layer_s(const float* __restrict__ src, int sp,
                                             float* __restrict__ dst, int dp,
                                             const float* __restrict__ w,
                                             const ull* __restrict__ bp,
                                             int len, int tid)
{
    int items = 4 * ((len + 3) >> 2);
    for (int it = tid; it < items; it += NT) {
        int cg = it & 3;
        int p  = (it >> 2) * 4;
        ull b01 = bp[cg * 2], b23 = bp[cg * 2 + 1];
        ull a0[4], a1[4];
#pragma unroll
        for (int t = 0; t < 4; t++) { a0[t] = b01; a1[t] = b23; }
#pragma unroll
        for (int ci = 0; ci < CIN; ci++) {
#pragma unroll
            for (int k = 0; k < 3; k++) {
                const ull* wp = (const ull*)&w[(ci * 3 + k) * 16 + cg * 4];
                ull w01 = wp[0], w23 = wp[1];
                const float* xr = &src[ci * sp + p + k * DIL];
#pragma unroll
                for (int t = 0; t < 4; t++) {
                    ull x2 = pk2(xr[t], xr[t]);
                    fma2(a0[t], w01, x2);
                    fma2(a1[t], w23, x2);
                }
            }
        }
        int c0 = cg * 4;
#pragma unroll
        for (int t = 0; t < 4; t++) {
            if (p + t < len) {
                float l, h;
                up2(a0[t], l, h);
                dst[(c0 + 0) * dp + p + t] = fmaxf(l, 0.f);
                dst[(c0 + 1) * dp + p + t] = fmaxf(h, 0.f);
                up2(a1[t], l, h);
                dst[(c0 + 2) * dp + p + t] = fmaxf(l, 0.f);
                dst[(c0 + 3) * dp + p + t] = fmaxf(h, 0.f);
            }
        }
    }
}

// ---------------- kernel 2: fused eeg dilated stack (R13, unchanged) ----------------
#define EP1 284
#define EP2 284
__global__ void __launch_bounds__(128)
k_eeg_stack(const float* __restrict__ w1, const float* __restrict__ b1,
            const float* __restrict__ w2, const float* __restrict__ b2,
            const float* __restrict__ w3, const float* __restrict__ b3)
{
    __shared__ __align__(16) float sA[16 * EP1];
    __shared__ __align__(16) float sB[16 * EP2];
    __shared__ __align__(16) float sw1[384], sw2[768], sw3[768];
    __shared__ ull bp1[8], bp2[8], bp3[8];

    int b  = blockIdx.y;
    int t0 = blockIdx.x * 256;
    int tid = threadIdx.x;
    int nOut = min(256, L3_LEN - t0);
    int n2 = nOut + 18, n1 = nOut + 24, nIn = nOut + 26;

    for (int i = tid; i < 384; i += 128) {
        int co = i & 15; int rem = i >> 4; int k = rem % 3; int ci = rem / 3;
        sw1[i] = w1[(co * 8 + ci) * 3 + k];
    }
    for (int i = tid; i < 768; i += 128) {
        int co = i & 15; int rem = i >> 4; int k = rem % 3; int ci = rem / 3;
        sw2[i] = w2[(co * 16 + ci) * 3 + k];
        sw3[i] = w3[(co * 16 + ci) * 3 + k];
    }
    if (tid < 8) {
        bp1[tid] = pk2(b1[2 * tid], b1[2 * tid + 1]);
        bp2[tid] = pk2(b2[2 * tid], b2[2 * tid + 1]);
        bp3[tid] = pk2(b3[2 * tid], b3[2 * tid + 1]);
    }

    const float* inb = g_x0 + ((size_t)b * 8) * TT + t0;
    for (int i = tid; i < 8 * nIn; i += 128) {
        int ci = i / nIn, q = i - ci * nIn;
        sB[ci * EP2 + q] = (t0 + q < TT) ? inb[(size_t)ci * TT + q] : 0.f;
    }
    __syncthreads();

    conv_layer_s<8, 1, 128>(sB, EP2, sA, EP1, sw1, bp1, n1, tid);
    __syncthreads();
    conv_layer_s<16, 3, 128>(sA, EP1, sB, EP2, sw2, bp2, n2, tid);
    __syncthreads();

    {
        float* ob = g_x3 + ((size_t)b * 16) * TT + t0;
        int items = 4 * ((nOut + 3) >> 2);
        for (int it = tid; it < items; it += 128) {
            int cg = it & 3;
            int p  = (it >> 2) * 4;
            ull b01 = bp3[cg * 2], b23 = bp3[cg * 2 + 1];
            ull a0[4], a1[4];
#pragma unroll
            for (int t = 0; t < 4; t++) { a0[t] = b01; a1[t] = b23; }
#pragma unroll
            for (int ci = 0; ci < 16; ci++) {
#pragma unroll
                for (int k = 0; k < 3; k++) {
                    const ull* wp = (const ull*)&sw3[(ci * 3 + k) * 16 + cg * 4];
                    ull w01 = wp[0], w23 = wp[1];
                    const float* xr = &sB[ci * EP2 + p + k * 9];
#pragma unroll
                    for (int t = 0; t < 4; t++) {
                        ull x2 = pk2(xr[t], xr[t]);
                        fma2(a0[t], w01, x2);
                        fma2(a1[t], w23, x2);
                    }
                }
            }
            float lo[4], hi[4], lo2[4], hi2[4];
#pragma unroll
            for (int t = 0; t < 4; t++) { up2(a0[t], lo[t], hi[t]); up2(a1[t], lo2[t], hi2[t]); }
            int c0 = cg * 4;
            if (p + 3 < nOut) {
                *(float4*)&ob[(size_t)(c0 + 0) * TT + p] =
                    make_float4(fmaxf(lo[0],0.f), fmaxf(lo[1],0.f), fmaxf(lo[2],0.f), fmaxf(lo[3],0.f));
                *(float4*)&ob[(size_t)(c0 + 1) * TT + p] =
                    make_float4(fmaxf(hi[0],0.f), fmaxf(hi[1],0.f), fmaxf(hi[2],0.f), fmaxf(hi[3],0.f));
                *(float4*)&ob[(size_t)(c0 + 2) * TT + p] =
                    make_float4(fmaxf(lo2[0],0.f), fmaxf(lo2[1],0.f), fmaxf(lo2[2],0.f), fmaxf(lo2[3],0.f));
                *(float4*)&ob[(size_t)(c0 + 3) * TT + p] =
                    make_float4(fmaxf(hi2[0],0.f), fmaxf(hi2[1],0.f), fmaxf(hi2[2],0.f), fmaxf(hi2[3],0.f));
            } else {
                for (int t = 0; t < 4; t++) {
                    if (p + t < nOut) {
                        ob[(size_t)(c0 + 0) * TT + p + t] = fmaxf(lo[t],  0.f);
                        ob[(size_t)(c0 + 1) * TT + p + t] = fmaxf(hi[t],  0.f);
                        ob[(size_t)(c0 + 2) * TT + p + t] = fmaxf(lo2[t], 0.f);
                        ob[(size_t)(c0 + 3) * TT + p + t] = fmaxf(hi2[t], 0.f);
                    }
                }
            }
        }
    }
}

// ---------------- kernel 3: eeg row norms ----------------
__global__ void k_eegnorm()
{
    __shared__ float red[256];
    int r = blockIdx.x;
    int tid = threadIdx.x;
    const float* p = g_x3 + (size_t)r * TT;
    float ss = 0.f;
    for (int t = tid; t < L3_LEN; t += 256) { float v = p[t]; ss += v * v; }
    red[tid] = ss; __syncthreads();
    for (int st = 128; st > 0; st >>= 1) {
        if (tid < st) red[tid] += red[tid + st];
        __syncthreads();
    }
    if (tid == 0) g_nx[r] = fmaxf(sqrtf(red[0]), 1e-8f);
}

// ---------------- kernel 4: zero accumulators ----------------
__global__ void k_zero()
{
    int i = blockIdx.x * 256 + threadIdx.x;
    if (i < BB * SS * 256) g_dot[i] = 0.f;
    if (i < BB * SS * 16)  g_nst2[i] = 0.f;
}

// ---------------- dup-operand conv layer (ull dup src; dup or float dst) ----------------
template <int CIN, int DIL, int SP, int DP, bool DUPOUT>
__device__ __forceinline__ void conv_dup(const ull* __restrict__ src,
                                         void* __restrict__ dstv,
                                         const float* __restrict__ w,
                                         const ull* __restrict__ bp,
                                         int len, int tid)
{
    int items = 4 * ((len + 3) >> 2);
    for (int it = tid; it < items; it += 128) {
        int cg = it & 3;
        int p  = (it >> 2) * 4;
        ull b01 = bp[cg * 2], b23 = bp[cg * 2 + 1];
        ull a0[4], a1[4];
#pragma unroll
        for (int t = 0; t < 4; t++) { a0[t] = b01; a1[t] = b23; }
#pragma unroll
        for (int ci = 0; ci < CIN; ci++) {
#pragma unroll
            for (int k = 0; k < 3; k++) {
                ulonglong2 wv = *(const ulonglong2*)&w[(ci * 3 + k) * 16 + cg * 4];
                const ull* xr = src + ci * SP + p + k * DIL;
                ull x0, x1, x2, x3;
                if ((k * DIL) & 1) {          // compile-time branch
                    x0 = xr[0]; x1 = xr[1]; x2 = xr[2]; x3 = xr[3];
                } else {                       // 16B-aligned: p%4==0, k*DIL even, SP even
                    ulonglong2 u = *(const ulonglong2*)xr;
                    ulonglong2 v = *(const ulonglong2*)(xr + 2);
                    x0 = u.x; x1 = u.y; x2 = v.x; x3 = v.y;
                }
                fma2(a0[0], wv.x, x0); fma2(a1[0], wv.y, x0);
                fma2(a0[1], wv.x, x1); fma2(a1[1], wv.y, x1);
                fma2(a0[2], wv.x, x2); fma2(a1[2], wv.y, x2);
                fma2(a0[3], wv.x, x3); fma2(a1[3], wv.y, x3);
            }
        }
        int c0 = cg * 4;
        if (DUPOUT) {
            ull* du = (ull*)dstv;
#pragma unroll
            for (int t = 0; t < 4; t++) {
                if (p + t < len) {
                    float l, h;
                    up2(a0[t], l, h);
                    l = fmaxf(l, 0.f); h = fmaxf(h, 0.f);
                    du[(c0 + 0) * DP + p + t] = pk2(l, l);
                    du[(c0 + 1) * DP + p + t] = pk2(h, h);
                    up2(a1[t], l, h);
                    l = fmaxf(l, 0.f); h = fmaxf(h, 0.f);
                    du[(c0 + 2) * DP + p + t] = pk2(l, l);
                    du[(c0 + 3) * DP + p + t] = pk2(h, h);
                }
            }
        } else {
            float* df = (float*)dstv;
#pragma unroll
            for (int t = 0; t < 4; t++) {
                if (p + t < len) {
                    float l, h;
                    up2(a0[t], l, h);
                    df[(c0 + 0) * DP + p + t] = fmaxf(l, 0.f);
                    df[(c0 + 1) * DP + p + t] = fmaxf(h, 0.f);
                    up2(a1[t], l, h);
                    df[(c0 + 2) * DP + p + t] = fmaxf(l, 0.f);
                    df[(c0 + 3) * DP + p + t] = fmaxf(h, 0.f);
                }
            }
        }
    }
}

// ---------------- kernel 5: stim stack + dot, 4 T-chunks per n, dup shared ----------------
#define TILE 192
#define NTILES 43          // ceil(8166/192)
#define DP1c 222           // l1 dup pitch (ull), even, ≡2 mod 4
#define DP2c 214           // l2 dup pitch (ull), even, ≡2 mod 4
#define PFc  196           // l3 / eeg-x float pitch
// dynamic smem layout (bytes)
#define OFF_XD2 28416      // XD1 at 0: 16*222*8 = 28416
#define OFF_IN  55808      // XD2: 16*214*8 = 27392 -> 55808
#define OFF_W2  56688      // sh_in 218*4=872 (+pad)
#define OFF_W3  59760
#define OFF_BP2 62832
#define OFF_BP3 62896
#define OFF_B1  62960
#define OFF_W1  63024
#define DSMEM   63232

__global__ void __launch_bounds__(128, 3)
k_stim(const float* __restrict__ stim,
       const float* __restrict__ ws1, const float* __restrict__ bs1,
       const float* __restrict__ ws2, const float* __restrict__ bs2,
       const float* __restrict__ ws3, const float* __restrict__ bs3)
{
    extern __shared__ __align__(16) char dyn[];
    ull*   xd1   = (ull*)(dyn);
    ull*   xd2   = (ull*)(dyn + OFF_XD2);
    float* sh_in = (float*)(dyn + OFF_IN);
    float* sh_w2 = (float*)(dyn + OFF_W2);
    float* sh_w3 = (float*)(dyn + OFF_W3);
    ull*   bp2   = (ull*)(dyn + OFF_BP2);
    ull*   bp3   = (ull*)(dyn + OFF_BP3);
    float* sh_b1 = (float*)(dyn + OFF_B1);
    float* sh_w1 = (float*)(dyn + OFF_W1);
    float* l3f   = (float*)xd1;   // layer-3 output (after l1 dead)
    float* xsf   = (float*)xd2;   // eeg x tile (after l2 dead)

    int bx = blockIdx.x;
    int n  = bx >> 2;             // n = s*B + b
    int cb = bx & 3;              // T-chunk 0..3
    int s  = n >> 6;
    int b  = n & 63;
    int tid = threadIdx.x;

    if (tid < 48) { int co = tid & 15, k = tid >> 4; sh_w1[k * 16 + co] = ws1[co * 3 + k]; }
    for (int i = tid; i < 768; i += 128) {
        int co = i & 15; int rem = i >> 4; int k = rem % 3; int ci = rem / 3;
        sh_w2[i] = ws2[(co * 16 + ci) * 3 + k];
        sh_w3[i] = ws3[(co * 16 + ci) * 3 + k];
    }
    if (tid < 8) {
        bp2[tid] = pk2(bs2[2 * tid], bs2[2 * tid + 1]);
        bp3[tid] = pk2(bs3[2 * tid], bs3[2 * tid + 1]);
    }
    if (tid < 16) sh_b1[tid] = bs1[tid];

    const float* seq   = stim + ((size_t)(b * SS + s)) * TT;
    const float* xbase = g_x3 + ((size_t)b * 16) * TT;

    // dot mapping: 2 t-subchunks x 64 (i,j) 2x2 tiles
    int chunk = tid >> 6;
    int q = tid & 63;
    int ip = q >> 3, jp = q & 7;
    int i0 = ip * 2, j0 = jp * 2;
    const ull* A0 = (const ull*)(l3f + (i0 + 0) * PFc);
    const ull* A1 = (const ull*)(l3f + (i0 + 1) * PFc);
    const ull* B0 = (const ull*)(xsf + (j0 + 0) * PFc);
    const ull* B1 = (const ull*)(xsf + (j0 + 1) * PFc);

    ull c00 = 0, c01 = 0, c10 = 0, c11 = 0, ss0 = 0, ss1 = 0;

    int ttEnd = min(cb * 11 + 11, NTILES);
    for (int tt = cb * 11; tt < ttEnd; tt++) {
        int t0 = tt * TILE;
        int nOut = min(TILE, L3_LEN - t0);    // always even
        int n1 = nOut + 24, n2 = nOut + 18, nIn = nOut + 26;

        // stage stimulus (writes sh_in only; prev dot reads xd1/xd2 regions)
        for (int i = tid; i < nIn; i += 128) sh_in[i] = seq[t0 + i];
        __syncthreads();   // ends prev dot + sh_in ready

        // layer 1: 1->16 dil 1, dup output (per-channel loop: conflict-free stores)
        for (int c = 0; c < 16; c++) {
            float wa = sh_w1[c], wb = sh_w1[16 + c], wc = sh_w1[32 + c], bb = sh_b1[c];
            for (int qq = tid; qq < n1; qq += 128) {
                float acc = bb + sh_in[qq] * wa + sh_in[qq + 1] * wb + sh_in[qq + 2] * wc;
                acc = fmaxf(acc, 0.f);
                xd1[c * DP1c + qq] = pk2(acc, acc);
            }
        }
        __syncthreads();

        // layer 2: 16->16 dil 3 (dup -> dup)
        conv_dup<16, 3, DP1c, DP2c, true>(xd1, xd2, sh_w2, bp2, n2, tid);
        __syncthreads();

        // layer 3: 16->16 dil 9 (dup -> float, into xd1 region)
        conv_dup<16, 9, DP2c, PFc, false>(xd2, l3f, sh_w3, bp3, nOut, tid);
        __syncthreads();

        // eeg x tile into xsf (xd2 region, l2 dead)
        for (int j = 0; j < 16; j++)
            for (int t = tid; t < nOut; t += 128)
                xsf[j * PFc + t] = xbase[(size_t)j * TT + t0 + t];
        __syncthreads();

        // dot accumulate (registers persist across tiles)
        int tBeg = chunk * 96;
        int tEnd = min(tBeg + 96, nOut);
        for (int t2 = tBeg >> 1; t2 < (tEnd >> 1); t2++) {
            ull a0 = A0[t2], a1 = A1[t2], b0 = B0[t2], b1 = B1[t2];
            fma2(c00, a0, b0); fma2(c01, a0, b1);
            fma2(c10, a1, b0); fma2(c11, a1, b1);
            if (jp == 0) { fma2(ss0, a0, a0); fma2(ss1, a1, a1); }
        }
        // no sync: next tile's first sync orders dot-reads vs layer-1 writes
    }

    // combine across the 4 chunk-blocks (and 2 t-subchunks) via atomics
    {
        float l, h;
        float* gd = g_dot + (size_t)n * 256;
        up2(c00, l, h); atomicAdd(&gd[(i0 + 0) * 16 + j0 + 0], l + h);
        up2(c01, l, h); atomicAdd(&gd[(i0 + 0) * 16 + j0 + 1], l + h);
        up2(c10, l, h); atomicAdd(&gd[(i0 + 1) * 16 + j0 + 0], l + h);
        up2(c11, l, h); atomicAdd(&gd[(i0 + 1) * 16 + j0 + 1], l + h);
        if (jp == 0) {
            up2(ss0, l, h); atomicAdd(&g_nst2[n * 16 + i0 + 0], l + h);
            up2(ss1, l, h); atomicAdd(&g_nst2[n * 16 + i0 + 1], l + h);
        }
    }
}

// ---------------- kernel 6: finalize cosine + linear ----------------
__global__ void k_final(const float* __restrict__ w_lin,
                        const float* __restrict__ b_lin,
                        float* __restrict__ out)
{
    __shared__ float red[256];
    int n = blockIdx.x;
    int s = n >> 6;
    int b = n & 63;
    int tid = threadIdx.x;
    int i = tid >> 4, j = tid & 15;

    float ni = fmaxf(sqrtf(g_nst2[n * 16 + i]), 1e-8f);
    float nj = g_nx[b * 16 + j];
    float v  = w_lin[tid] * g_dot[(size_t)n * 256 + tid] / (ni * nj);

    red[tid] = v; __syncthreads();
    for (int st = 128; st > 0; st >>= 1) {
        if (tid < st) red[tid] += red[tid + st];
        __syncthreads();
    }
    if (tid == 0) out[b * SS + s] = red[0] + b_lin[0];
}

// ---------------- launch ----------------
extern "C" void kernel_launch(void* const* d_in, const int* in_sizes, int n_in,
                              void* d_out, int out_size)
{
    const float* eeg   = (const float*)d_in[0];
    const float* stim  = (const float*)d_in[1];
    const float* w_eeg = (const float*)d_in[2];
    const float* b_eeg = (const float*)d_in[3];
    const float* w_e1  = (const float*)d_in[4];
    const float* b_e1  = (const float*)d_in[5];
    const float* w_e2  = (const float*)d_in[6];
    const float* b_e2  = (const float*)d_in[7];
    const float* w_e3  = (const float*)d_in[8];
    const float* b_e3  = (const float*)d_in[9];
    const float* w_s1  = (const float*)d_in[10];
    const float* b_s1  = (const float*)d_in[11];
    const float* w_s2  = (const float*)d_in[12];
    const float* b_s2  = (const float*)d_in[13];
    const float* w_s3  = (const float*)d_in[14];
    const float* b_s3  = (const float*)d_in[15];
    const float* w_lin = (const float*)d_in[16];
    const float* b_lin = (const float*)d_in[17];
    float* out = (float*)d_out;

    static int smem_set = 0;
    if (!smem_set) {
        cudaFuncSetAttribute(k_stim, cudaFuncAttributeMaxDynamicSharedMemorySize, DSMEM);
        smem_set = 1;
    }

    k_head<<<(BB * TT) / 256, 256>>>(eeg, w_eeg, b_eeg);
    k_eeg_stack<<<dim3(32, BB), 128>>>(w_e1, b_e1, w_e2, b_e2, w_e3, b_e3);
    k_eegnorm<<<BB * 16, 256>>>();

    k_zero<<<(BB * SS * 256) / 256, 256>>>();

    k_stim<<<BB * SS * 4, 128, DSMEM>>>(stim, w_s1, b_s1, w_s2, b_s2, w_s3, b_s3);

    k_final<<<BB * SS, 256>>>(w_lin, b_lin, out);
}

// round 15
// speedup vs baseline: 1.8005x; 1.8005x over previous
#include <cuda_runtime.h>
#include <cuda_bf16.h>
#include <math.h>

typedef unsigned long long ull;

// ---------------- problem constants ----------------
#define BB 64
#define SS 8
#define TT 8192
#define L1_LEN 8190
#define L2_LEN 8184
#define L3_LEN 8166

// ---------------- packed f32x2 helpers ----------------
__device__ __forceinline__ ull pk2(float lo, float hi) {
    ull r; asm("mov.b64 %0, {%1, %2};" : "=l"(r) : "f"(lo), "f"(hi)); return r;
}
__device__ __forceinline__ void up2(ull v, float& lo, float& hi) {
    asm("mov.b64 {%0, %1}, %2;" : "=f"(lo), "=f"(hi) : "l"(v));
}
__device__ __forceinline__ void fma2(ull& d, ull a, ull b) {
    asm("fma.rn.f32x2 %0, %1, %2, %0;" : "+l"(d) : "l"(a), "l"(b));
}

// ---------------- device scratch ----------------
__device__ float g_x0[(size_t)BB * 8  * TT];   // eeg after 1x1 head
__device__ float g_x3[(size_t)BB * 16 * TT];   // eeg final features
__device__ float g_nx[BB * 16];                // eeg norms
__device__ float g_nst2[BB * SS * 16];         // stim sumsq accumulators
__device__ float g_dot[(size_t)BB * SS * 256]; // dot accumulators

// ---------------- kernel 1: eeg 1x1 head (64 -> 8) ----------------
__global__ void k_head(const float* __restrict__ eeg,
                       const float* __restrict__ w,
                       const float* __restrict__ bias)
{
    __shared__ float sh_w[512];
    __shared__ float sh_b[8];
    int tid = threadIdx.x;
    for (int i = tid; i < 512; i += 256) sh_w[i] = w[i];
    if (tid < 8) sh_b[tid] = bias[tid];
    __syncthreads();

    size_t idx = (size_t)blockIdx.x * 256 + tid;
    int b = (int)(idx >> 13);
    int t = (int)(idx & (TT - 1));

    const float4* ep = (const float4*)(eeg + idx * 64);
    float acc[8];
#pragma unroll
    for (int c = 0; c < 8; c++) acc[c] = sh_b[c];
#pragma unroll
    for (int q = 0; q < 16; q++) {
        float4 v = ep[q];
#pragma unroll
        for (int c = 0; c < 8; c++) {
            acc[c] += v.x * sh_w[c * 64 + q * 4 + 0]
                    + v.y * sh_w[c * 64 + q * 4 + 1]
                    + v.z * sh_w[c * 64 + q * 4 + 2]
                    + v.w * sh_w[c * 64 + q * 4 + 3];
        }
    }
    float* ob = g_x0 + ((size_t)b * 8) * TT + t;
#pragma unroll
    for (int c = 0; c < 8; c++) ob[(size_t)c * TT] = acc[c];
}

// ---------------- R13 conv body (float shared) ----------------
template <int CIN, int DIL, int NT>
__device__ __forceinline__ void conv_layer_s(const float* __restrict__ src, int sp,
                                             float* __restrict__ dst, int dp,
                                             const float* __restrict__ w,
                                             const ull* __restrict__ bp,
                                             int len, int tid)
{
    int items = 4 * ((len + 3) >> 2);
    for (int it = tid; it < items; it += NT) {
        int cg = it & 3;
        int p  = (it >> 2) * 4;
        ull b01 = bp[cg * 2], b23 = bp[cg * 2 + 1];
        ull a0[4], a1[4];
#pragma unroll
        for (int t = 0; t < 4; t++) { a0[t] = b01; a1[t] = b23; }
#pragma unroll
        for (int ci = 0; ci < CIN; ci++) {
#pragma unroll
            for (int k = 0; k < 3; k++) {
                const ull* wp = (const ull*)&w[(ci * 3 + k) * 16 + cg * 4];
                ull w01 = wp[0], w23 = wp[1];
                const float* xr = &src[ci * sp + p + k * DIL];
#pragma unroll
                for (int t = 0; t < 4; t++) {
                    ull x2 = pk2(xr[t], xr[t]);
                    fma2(a0[t], w01, x2);
                    fma2(a1[t], w23, x2);
                }
            }
        }
        int c0 = cg * 4;
#pragma unroll
        for (int t = 0; t < 4; t++) {
            if (p + t < len) {
                float l, h;
                up2(a0[t], l, h);
                dst[(c0 + 0) * dp + p + t] = fmaxf(l, 0.f);
                dst[(c0 + 1) * dp + p + t] = fmaxf(h, 0.f);
                up2(a1[t], l, h);
                dst[(c0 + 2) * dp + p + t] = fmaxf(l, 0.f);
                dst[(c0 + 3) * dp + p + t] = fmaxf(h, 0.f);
            }
        }
    }
}

// ---------------- kernel 2: fused eeg dilated stack (R13, unchanged) ----------------
#define EP1 284
#define EP2 284
__global__ void __launch_bounds__(128)
k_eeg_stack(const float* __restrict__ w1, const float* __restrict__ b1,
            const float* __restrict__ w2, const float* __restrict__ b2,
            const float* __restrict__ w3, const float* __restrict__ b3)
{
    __shared__ __align__(16) float sA[16 * EP1];
    __shared__ __align__(16) float sB[16 * EP2];
    __shared__ __align__(16) float sw1[384], sw2[768], sw3[768];
    __shared__ ull bp1[8], bp2[8], bp3[8];

    int b  = blockIdx.y;
    int t0 = blockIdx.x * 256;
    int tid = threadIdx.x;
    int nOut = min(256, L3_LEN - t0);
    int n2 = nOut + 18, n1 = nOut + 24, nIn = nOut + 26;

    for (int i = tid; i < 384; i += 128) {
        int co = i & 15; int rem = i >> 4; int k = rem % 3; int ci = rem / 3;
        sw1[i] = w1[(co * 8 + ci) * 3 + k];
    }
    for (int i = tid; i < 768; i += 128) {
        int co = i & 15; int rem = i >> 4; int k = rem % 3; int ci = rem / 3;
        sw2[i] = w2[(co * 16 + ci) * 3 + k];
        sw3[i] = w3[(co * 16 + ci) * 3 + k];
    }
    if (tid < 8) {
        bp1[tid] = pk2(b1[2 * tid], b1[2 * tid + 1]);
        bp2[tid] = pk2(b2[2 * tid], b2[2 * tid + 1]);
        bp3[tid] = pk2(b3[2 * tid], b3[2 * tid + 1]);
    }

    const float* inb = g_x0 + ((size_t)b * 8) * TT + t0;
    for (int i = tid; i < 8 * nIn; i += 128) {
        int ci = i / nIn, q = i - ci * nIn;
        sB[ci * EP2 + q] = (t0 + q < TT) ? inb[(size_t)ci * TT + q] : 0.f;
    }
    __syncthreads();

    conv_layer_s<8, 1, 128>(sB, EP2, sA, EP1, sw1, bp1, n1, tid);
    __syncthreads();
    conv_layer_s<16, 3, 128>(sA, EP1, sB, EP2, sw2, bp2, n2, tid);
    __syncthreads();

    {
        float* ob = g_x3 + ((size_t)b * 16) * TT + t0;
        int items = 4 * ((nOut + 3) >> 2);
        for (int it = tid; it < items; it += 128) {
            int cg = it & 3;
            int p  = (it >> 2) * 4;
            ull b01 = bp3[cg * 2], b23 = bp3[cg * 2 + 1];
            ull a0[4], a1[4];
#pragma unroll
            for (int t = 0; t < 4; t++) { a0[t] = b01; a1[t] = b23; }
#pragma unroll
            for (int ci = 0; ci < 16; ci++) {
#pragma unroll
                for (int k = 0; k < 3; k++) {
                    const ull* wp = (const ull*)&sw3[(ci * 3 + k) * 16 + cg * 4];
                    ull w01 = wp[0], w23 = wp[1];
                    const float* xr = &sB[ci * EP2 + p + k * 9];
#pragma unroll
                    for (int t = 0; t < 4; t++) {
                        ull x2 = pk2(xr[t], xr[t]);
                        fma2(a0[t], w01, x2);
                        fma2(a1[t], w23, x2);
                    }
                }
            }
            float lo[4], hi[4], lo2[4], hi2[4];
#pragma unroll
            for (int t = 0; t < 4; t++) { up2(a0[t], lo[t], hi[t]); up2(a1[t], lo2[t], hi2[t]); }
            int c0 = cg * 4;
            if (p + 3 < nOut) {
                *(float4*)&ob[(size_t)(c0 + 0) * TT + p] =
                    make_float4(fmaxf(lo[0],0.f), fmaxf(lo[1],0.f), fmaxf(lo[2],0.f), fmaxf(lo[3],0.f));
                *(float4*)&ob[(size_t)(c0 + 1) * TT + p] =
                    make_float4(fmaxf(hi[0],0.f), fmaxf(hi[1],0.f), fmaxf(hi[2],0.f), fmaxf(hi[3],0.f));
                *(float4*)&ob[(size_t)(c0 + 2) * TT + p] =
                    make_float4(fmaxf(lo2[0],0.f), fmaxf(lo2[1],0.f), fmaxf(lo2[2],0.f), fmaxf(lo2[3],0.f));
                *(float4*)&ob[(size_t)(c0 + 3) * TT + p] =
                    make_float4(fmaxf(hi2[0],0.f), fmaxf(hi2[1],0.f), fmaxf(hi2[2],0.f), fmaxf(hi2[3],0.f));
            } else {
                for (int t = 0; t < 4; t++) {
                    if (p + t < nOut) {
                        ob[(size_t)(c0 + 0) * TT + p + t] = fmaxf(lo[t],  0.f);
                        ob[(size_t)(c0 + 1) * TT + p + t] = fmaxf(hi[t],  0.f);
                        ob[(size_t)(c0 + 2) * TT + p + t] = fmaxf(lo2[t], 0.f);
                        ob[(size_t)(c0 + 3) * TT + p + t] = fmaxf(hi2[t], 0.f);
                    }
                }
            }
        }
    }
}

// ---------------- kernel 3: eeg row norms ----------------
__global__ void k_eegnorm()
{
    __shared__ float red[256];
    int r = blockIdx.x;
    int tid = threadIdx.x;
    const float* p = g_x3 + (size_t)r * TT;
    float ss = 0.f;
    for (int t = tid; t < L3_LEN; t += 256) { float v = p[t]; ss += v * v; }
    red[tid] = ss; __syncthreads();
    for (int st = 128; st > 0; st >>= 1) {
        if (tid < st) red[tid] += red[tid + st];
        __syncthreads();
    }
    if (tid == 0) g_nx[r] = fmaxf(sqrtf(red[0]), 1e-8f);
}

// ---------------- kernel 4: zero accumulators ----------------
__global__ void k_zero()
{
    int i = blockIdx.x * 256 + threadIdx.x;
    if (i < BB * SS * 256) g_dot[i] = 0.f;
    if (i < BB * SS * 16)  g_nst2[i] = 0.f;
}

// ---------------- kernel 5: stim stack + dot (R13 body, 4-way T-chunk split) ----------------
// grid = BB*SS*4 = 2048; block 128. Chunk cb handles tiles [cb*8, cb*8+8) of 32.
#define P1 284
#define P2 280
#define P3 260
__global__ void __launch_bounds__(128)
k_stim(const float* __restrict__ stim,
       const float* __restrict__ ws1, const float* __restrict__ bs1,
       const float* __restrict__ ws2, const float* __restrict__ bs2,
       const float* __restrict__ ws3, const float* __restrict__ bs3)
{
    __shared__ __align__(16) float bufA[16 * P1];   // l1 / l3
    __shared__ __align__(16) float bufB[16 * P2];   // l2 / eeg x
    __shared__ __align__(16) float sh_in[P1];
    __shared__ __align__(16) float sh_w2[768];
    __shared__ __align__(16) float sh_w3[768];
    __shared__ float sh_w1[48];
    __shared__ ull sh_bp2[8], sh_bp3[8];
    __shared__ float sh_b1[16];

    int bx = blockIdx.x;
    int n  = bx >> 2;             // n = s*B + b
    int cb = bx & 3;              // T-chunk 0..3
    int s  = n >> 6;
    int b  = n & 63;
    int tid = threadIdx.x;

    if (tid < 48) { int co = tid & 15, k = tid >> 4; sh_w1[k * 16 + co] = ws1[co * 3 + k]; }
    for (int i = tid; i < 768; i += 128) {
        int co = i & 15; int rem = i >> 4; int k = rem % 3; int ci = rem / 3;
        sh_w2[i] = ws2[(co * 16 + ci) * 3 + k];
        sh_w3[i] = ws3[(co * 16 + ci) * 3 + k];
    }
    if (tid < 8) {
        sh_bp2[tid] = pk2(bs2[2 * tid], bs2[2 * tid + 1]);
        sh_bp3[tid] = pk2(bs3[2 * tid], bs3[2 * tid + 1]);
    }
    if (tid < 16) sh_b1[tid] = bs1[tid];

    const float* seq   = stim + ((size_t)(b * SS + s)) * TT;
    const float* xbase = g_x3 + ((size_t)b * 16) * TT;

    // dot mapping: 2 t-subchunks x 64 (i,j) 2x2 tiles (R13)
    int chunk = tid >> 6;
    int q = tid & 63;
    int ip = q >> 3, jp = q & 7;
    int i0 = ip * 2, j0 = jp * 2;
    const ull* A0 = (const ull*)(bufA + (i0 + 0) * P3);
    const ull* A1 = (const ull*)(bufA + (i0 + 1) * P3);
    const ull* B0 = (const ull*)(bufB + (j0 + 0) * P3);
    const ull* B1 = (const ull*)(bufB + (j0 + 1) * P3);

    ull c00 = 0, c01 = 0, c10 = 0, c11 = 0, ss0 = 0, ss1 = 0;

    for (int tile = cb * 8; tile < cb * 8 + 8; tile++) {
        int t0 = tile * 256;
        int nOut = min(256, L3_LEN - t0);
        int n1 = nOut + 24, n2 = nOut + 18, nIn = nOut + 26;

        // stage stimulus tile (writes only sh_in; prior dot reads only bufA/bufB)
        for (int i = tid; i < nIn; i += 128) sh_in[i] = seq[t0 + i];
        __syncthreads();   // ends prev dot (bufA/bufB safe) + sh_in ready

        // layer 1: 1 -> 16, dil 1
        for (int it = tid; it < 16 * n1; it += 128) {
            int c = it & 15, qq = it >> 4;
            float acc = sh_b1[c];
            acc += sh_in[qq + 0] * sh_w1[ 0 + c];
            acc += sh_in[qq + 1] * sh_w1[16 + c];
            acc += sh_in[qq + 2] * sh_w1[32 + c];
            bufA[c * P1 + qq] = fmaxf(acc, 0.f);
        }
        __syncthreads();

        conv_layer_s<16, 3, 128>(bufA, P1, bufB, P2, sh_w2, sh_bp2, n2, tid);
        __syncthreads();

        conv_layer_s<16, 9, 128>(bufB, P2, bufA, P3, sh_w3, sh_bp3, nOut, tid);
        __syncthreads();

        // eeg x tile into bufB (l2 dead)
        for (int i = tid; i < 16 * 256; i += 128) {
            int j = i >> 8, t = i & 255;
            if (t < nOut) bufB[j * P3 + t] = xbase[(size_t)j * TT + t0 + t];
        }
        __syncthreads();

        // dot accumulate (registers persist across tiles)
        int tBeg = chunk * 128;
        int tEnd = min(tBeg + 128, nOut);
        for (int t2 = tBeg >> 1; t2 < (tEnd >> 1); t2++) {
            ull a0 = A0[t2], a1 = A1[t2], b0 = B0[t2], b1 = B1[t2];
            fma2(c00, a0, b0); fma2(c01, a0, b1);
            fma2(c10, a1, b0); fma2(c11, a1, b1);
            if (jp == 0) { fma2(ss0, a0, a0); fma2(ss1, a1, a1); }
        }
        // no sync: next tile's first sync orders dot-reads vs layer-1 writes
    }

    // combine across the 4 chunk-blocks (and 2 t-subchunks) via atomics
    {
        float l, h;
        float* gd = g_dot + (size_t)n * 256;
        up2(c00, l, h); atomicAdd(&gd[(i0 + 0) * 16 + j0 + 0], l + h);
        up2(c01, l, h); atomicAdd(&gd[(i0 + 0) * 16 + j0 + 1], l + h);
        up2(c10, l, h); atomicAdd(&gd[(i0 + 1) * 16 + j0 + 0], l + h);
        up2(c11, l, h); atomicAdd(&gd[(i0 + 1) * 16 + j0 + 1], l + h);
        if (jp == 0) {
            up2(ss0, l, h); atomicAdd(&g_nst2[n * 16 + i0 + 0], l + h);
            up2(ss1, l, h); atomicAdd(&g_nst2[n * 16 + i0 + 1], l + h);
        }
    }
}

// ---------------- kernel 6: finalize cosine + linear ----------------
__global__ void k_final(const float* __restrict__ w_lin,
                        const float* __restrict__ b_lin,
                        float* __restrict__ out)
{
    __shared__ float red[256];
    int n = blockIdx.x;
    int s = n >> 6;
    int b = n & 63;
    int tid = threadIdx.x;
    int i = tid >> 4, j = tid & 15;

    float ni = fmaxf(sqrtf(g_nst2[n * 16 + i]), 1e-8f);
    float nj = g_nx[b * 16 + j];
    float v  = w_lin[tid] * g_dot[(size_t)n * 256 + tid] / (ni * nj);

    red[tid] = v; __syncthreads();
    for (int st = 128; st > 0; st >>= 1) {
        if (tid < st) red[tid] += red[tid + st];
        __syncthreads();
    }
    if (tid == 0) out[b * SS + s] = red[0] + b_lin[0];
}

// ---------------- launch ----------------
extern "C" void kernel_launch(void* const* d_in, const int* in_sizes, int n_in,
                              void* d_out, int out_size)
{
    const float* eeg   = (const float*)d_in[0];
    const float* stim  = (const float*)d_in[1];
    const float* w_eeg = (const float*)d_in[2];
    const float* b_eeg = (const float*)d_in[3];
    const float* w_e1  = (const float*)d_in[4];
    const float* b_e1  = (const float*)d_in[5];
    const float* w_e2  = (const float*)d_in[6];
    const float* b_e2  = (const float*)d_in[7];
    const float* w_e3  = (const float*)d_in[8];
    const float* b_e3  = (const float*)d_in[9];
    const float* w_s1  = (const float*)d_in[10];
    const float* b_s1  = (const float*)d_in[11];
    const float* w_s2  = (const float*)d_in[12];
    const float* b_s2  = (const float*)d_in[13];
    const float* w_s3  = (const float*)d_in[14];
    const float* b_s3  = (const float*)d_in[15];
    const float* w_lin = (const float*)d_in[16];
    const float* b_lin = (const float*)d_in[17];
    float* out = (float*)d_out;

    k_head<<<(BB * TT) / 256, 256>>>(eeg, w_eeg, b_eeg);
    k_eeg_stack<<<dim3(32, BB), 128>>>(w_e1, b_e1, w_e2, b_e2, w_e3, b_e3);
    k_eegnorm<<<BB * 16, 256>>>();

    k_zero<<<(BB * SS * 256) / 256, 256>>>();

    k_stim<<<BB * SS * 4, 128>>>(stim, w_s1, b_s1, w_s2, b_s2, w_s3, b_s3);

    k_final<<<BB * SS, 256>>>(w_lin, b_lin, out);
}